// round 1
// baseline (speedup 1.0000x reference)
#include <cuda_runtime.h>
#include <math.h>
#include <stdint.h>
#include <stddef.h>

// DBN beat decoder: Viterbi over bar-pointer model.
// intervals tau = 28..109 (82 tempi), S = 5617 states, B = 4, T = 6000.
#define NI      82
#define S_TOT   5617
#define S_PAD   5632
#define T_LEN   6000
#define BATCH   4
#define TPB     1024
#define TRB     384      // transition threads (12 warps, 4 per tempo j)
#define SHB     640      // shift threads
#define TSTRIDE 104      // trans row stride (104 % 32 == 8 -> conflict-free 4-row access)

// Backpointers: argmax tempo index per (batch, step, tempo). ~2MB, static device global.
__device__ unsigned char g_bp[(size_t)BATCH * (T_LEN - 1) * NI];

__device__ __forceinline__ int first_of(int i) { return 28 * i + (i * (i - 1)) / 2; }
__device__ __forceinline__ int last_of(int i)  { return first_of(i) + 27 + i; }

__global__ __launch_bounds__(TPB, 1)
void dbn_beat_kernel(const float* __restrict__ logit, float* __restrict__ out)
{
    extern __shared__ char smem_raw[];
    float* trans   = (float*)smem_raw;              // 82*104 floats
    float* dbuf    = trans + NI * TSTRIDE;          // 2 * 5632 floats (double buffer)
    float* blp     = dbuf + 2 * S_PAD;              // 6000 beat log-probs
    float* nlp     = blp + T_LEN;                   // 6000 non-beat log-probs
    int*   last_sh = (int*)(nlp + T_LEN);           // 82
    unsigned char* isf = (unsigned char*)(last_sh + NI);  // 5632 pos0 flags
    float* redv    = (float*)(isf + S_PAD);         // 32
    int*   redi    = (int*)(redv + 32);             // 32

    const int tid = threadIdx.x;
    const int b   = blockIdx.x;
    const float* lg = logit + (size_t)b * T_LEN;
    unsigned char* bpb = g_bp + (size_t)b * (T_LEN - 1) * NI;

    // ---- setup phase 1: tables ----
    if (tid < NI) last_sh[tid] = last_of(tid);
    for (int s = tid; s < S_PAD; s += TPB) isf[s] = 0;
    __syncthreads();

    if (tid < NI) isf[first_of(tid)] = 1;

    // trans_log row (fp64 like the numpy reference; row max is exactly 0 at j==i)
    if (tid < NI) {
        double ti = (double)(28 + tid);
        double sum = 0.0;
        for (int jj = 0; jj < NI; ++jj) {
            double r = -100.0 * fabs((double)(28 + jj) / ti - 1.0);
            sum += exp(r);
        }
        double ls = log(sum);
        for (int jj = 0; jj < NI; ++jj) {
            double r = -100.0 * fabs((double)(28 + jj) / ti - 1.0);
            trans[tid * TSTRIDE + jj] = (float)(r - ls);
        }
    }

    // emissions: log_sigmoid(x) = min(x,0) - log1p(exp(-|x|)) (matches JAX lowering)
    for (int t = tid; t < T_LEN; t += TPB) {
        float x  = lg[t];
        float l1 = log1pf(expf(-fabsf(x)));
        blp[t] = fminf(x, 0.0f) - l1;
        nlp[t] = fminf(-x, 0.0f) - l1;
    }
    __syncthreads();

    // ---- setup phase 2: delta0 + per-thread role state ----
    const float logS = logf((float)S_TOT);
    for (int s = tid; s < S_TOT; s += TPB)
        dbuf[s] = (isf[s] ? blp[0] : nlp[0]) - logS;

    int jidx = 0, q = 0, firstj = 0;
    bool act = false;
    int lastreg[21];
    unsigned int vmask = 0;

    if (tid < TRB) {
        jidx = tid >> 2; q = tid & 3;
        act = (jidx < NI);
        firstj = first_of(jidx);
#pragma unroll
        for (int k = 0; k < 21; ++k) {
            int i = q + 4 * k;
            int ii = (i < NI) ? i : 0;
            lastreg[k] = last_of(ii);
        }
    } else {
        int base = tid - TRB;
#pragma unroll
        for (int k = 0; k < 9; ++k) {
            int s = base + k * SHB;
            if (s > 0 && s < S_TOT && !isf[s]) vmask |= (1u << k);
        }
    }
    __syncthreads();

    // ---- main Viterbi loop: one barrier per frame ----
    for (int t = 1; t < T_LEN; ++t) {
        const float* dc = dbuf + ((t + 1) & 1) * S_PAD;   // delta at t-1
        float*       dn = dbuf + (t & 1) * S_PAD;         // delta at t

        if (tid < TRB) {
            float best = -INFINITY;
            int   bi   = 0x7fffffff;
            if (act) {
                const float* trow = trans + q * TSTRIDE + jidx;
#pragma unroll
                for (int k = 0; k < 20; ++k) {
                    float c = dc[lastreg[k]] + trow[k * (4 * TSTRIDE)];
                    if (c > best) { best = c; bi = q + 4 * k; }
                }
                if (q < 2) {
                    float c = dc[lastreg[20]] + trow[20 * (4 * TSTRIDE)];
                    if (c > best) { best = c; bi = q + 80; }
                }
            }
            // combine the 4 partials per tempo j: larger value wins, tie -> smaller i
#pragma unroll
            for (int off = 1; off < 4; off <<= 1) {
                float ov = __shfl_xor_sync(0xffffffffu, best, off);
                int   oi = __shfl_xor_sync(0xffffffffu, bi,   off);
                if (ov > best || (ov == best && oi < bi)) { best = ov; bi = oi; }
            }
            if (act && q == 0) {
                dn[firstj] = best + blp[t];
                bpb[(size_t)(t - 1) * NI + jidx] = (unsigned char)bi;
            }
        } else {
            float nb = nlp[t];
            int base = tid - TRB;
#pragma unroll
            for (int k = 0; k < 9; ++k) {
                if (vmask & (1u << k)) {
                    int s = base + k * SHB;
                    dn[s] = dc[s - 1] + nb;
                }
            }
        }
        __syncthreads();
    }

    // ---- argmax over final delta (first-max wins) ----
    const float* df = dbuf + ((T_LEN - 1) & 1) * S_PAD;
    float* outb = out + (size_t)b * T_LEN;
    for (int t = tid; t < T_LEN; t += TPB) outb[t] = 0.0f;

    float bv = -INFINITY;
    int   bs = 0x7fffffff;
    for (int s = tid; s < S_TOT; s += TPB) {
        float v = df[s];
        if (v > bv) { bv = v; bs = s; }
    }
#pragma unroll
    for (int off = 16; off >= 1; off >>= 1) {
        float ov = __shfl_xor_sync(0xffffffffu, bv, off);
        int   oi = __shfl_xor_sync(0xffffffffu, bs, off);
        if (ov > bv || (ov == bv && oi < bs)) { bv = ov; bs = oi; }
    }
    if ((tid & 31) == 0) { redv[tid >> 5] = bv; redi[tid >> 5] = bs; }
    __syncthreads();

    // ---- backtrace (thread 0; only beat frames get written, zeros already set) ----
    if (tid == 0) {
        for (int w = 1; w < 32; ++w) {
            if (redv[w] > bv || (redv[w] == bv && redi[w] < bs)) { bv = redv[w]; bs = redi[w]; }
        }
        int s = bs;
        int j = 0;
        while (j < NI - 1 && first_of(j + 1) <= s) ++j;
        int pos = s - first_of(j);

        for (int t = T_LEN - 1; t >= 1; --t) {
            if (pos == 0) {
                float x  = lg[t];
                float sg = 1.0f / (1.0f + expf(-x));
                if (sg >= 0.05f) outb[t] = 1.0f;
                int i = bpb[(size_t)(t - 1) * NI + j];
                j = i;
                pos = 27 + i;          // tau_i - 1
            } else {
                --pos;
            }
        }
        if (pos == 0) {
            float x  = lg[0];
            float sg = 1.0f / (1.0f + expf(-x));
            if (sg >= 0.05f) outb[0] = 1.0f;
        }
    }
}

extern "C" void kernel_launch(void* const* d_in, const int* in_sizes, int n_in,
                              void* d_out, int out_size)
{
    (void)in_sizes; (void)n_in; (void)out_size;
    const float* logit = (const float*)d_in[0];
    float* out = (float*)d_out;

    // trans(82*104) + dbuf(2*5632) + blp/nlp(2*6000) floats + last(82 ints)
    // + isf(5632 bytes) + red arrays
    const size_t smem = (size_t)(NI * TSTRIDE + 2 * S_PAD + 2 * T_LEN) * 4
                      + NI * 4 + S_PAD + 64 * 4;
    cudaFuncSetAttribute(dbn_beat_kernel,
                         cudaFuncAttributeMaxDynamicSharedMemorySize, (int)smem);
    dbn_beat_kernel<<<BATCH, TPB, smem>>>(logit, out);
}

// round 2
// speedup vs baseline: 2.2042x; 2.2042x over previous
#include <cuda_runtime.h>
#include <math.h>
#include <stdint.h>
#include <stddef.h>

// DBN beat decoder, lag-28 chunked formulation.
// tau = 28..109 (82 tempi), S = 5617, B = 4, T = 6000.
#define NI     82
#define TROW   84      // padded trans row (float4-aligned)
#define LROW   88      // padded L row
#define S_TOT  5617
#define T_LEN  6000
#define BATCH  4
#define TPB    1024
#define RING   256
#define CHUNK  28

// Exact L values (delta_{t-1}[last[i]]) for lazy backpointer recovery. ~7.9MB.
__device__ float g_L[(size_t)BATCH * T_LEN * NI];

__device__ __forceinline__ int first_of(int i) { return 28 * i + (i * (i - 1)) / 2; }

__global__ __launch_bounds__(TPB, 1)
void dbn_kernel(const float* __restrict__ logit, float* __restrict__ out)
{
    extern __shared__ char smraw[];
    float* trans_c = (float*)smraw;               // [82][84]: trans_c[j][i] = trans_log[i][j]
    float* Fring   = trans_c + NI * TROW;         // [256][84]: F_t[j] ring (t & 255)
    float* Lbuf    = Fring + RING * TROW;         // [30][88]: current chunk L[f][i]
    float* blp     = Lbuf + 30 * LROW;            // 6000
    float* nlp     = blp + T_LEN;                 // 6000 (16B aligned)
    float* redv    = nlp + T_LEN;                 // 32
    int*   redi    = (int*)(redv + 32);           // 32

    const int tid = threadIdx.x;
    const int b   = blockIdx.x;
    const float* lg = logit + (size_t)b * T_LEN;
    float* Lg   = g_L + (size_t)b * T_LEN * NI;
    float* outb = out + (size_t)b * T_LEN;

    // ---- setup: transition matrix (fp64, matches numpy), emissions, pads ----
    if (tid < NI) {
        double ti = (double)(28 + tid);
        double sum = 0.0;
        for (int jj = 0; jj < NI; ++jj)
            sum += exp(-100.0 * fabs((double)(28 + jj) / ti - 1.0));
        double ls = log(sum);
        for (int jj = 0; jj < NI; ++jj) {
            double r = -100.0 * fabs((double)(28 + jj) / ti - 1.0);
            trans_c[jj * TROW + tid] = (float)(r - ls);   // row i=tid into column slot
        }
    }
    if (tid < 2 * NI) {           // pad i = 82,83 of every j-row
        int j = tid >> 1;
        trans_c[j * TROW + 82 + (tid & 1)] = -1e30f;
    }
    for (int k = tid; k < 30 * LROW; k += TPB) Lbuf[k] = -1e30f;
    for (int t = tid; t < T_LEN; t += TPB) {
        float x  = lg[t];
        float l1 = log1pf(expf(-fabsf(x)));
        blp[t] = fminf(x, 0.0f) - l1;
        nlp[t] = fminf(-x, 0.0f) - l1;
    }
    __syncthreads();

    const float logS = logf((float)S_TOT);
    if (tid < NI) Fring[0 * TROW + tid] = blp[0] - logS;   // F_0[j] = delta0[first[j]]
    __syncthreads();
    const float nlp0m = nlp[0] - logS;                     // delta0 at non-first states
    const float4* nlp4 = (const float4*)nlp;

    // ---- main loop: 215 chunks of up to 28 frames ----
    const int NCH = (T_LEN - 1 + CHUNK - 1) / CHUNK;
    for (int c = 0; c < NCH; ++c) {
        const int t0 = 1 + CHUNK * c;
        int NF = T_LEN - t0; if (NF > CHUNK) NF = CHUNK;

        // Phase A: 2296 exact chains -> L_{t-1}[j] for t in chunk
#pragma unroll
        for (int r = 0; r < 3; ++r) {
            int id = r * TPB + tid;
            if (id < NF * NI) {
                int f = id / NI;
                int j = id - f * NI;
                int t = t0 + f;
                int tau = 28 + j;
                int st = t - tau;
                float acc; int u;
                if (st >= 0) { acc = Fring[(st & (RING - 1)) * TROW + j]; u = st + 1; }
                else         { acc = nlp0m;                               u = 1; }
                while ((u & 3) && u < t) { acc += nlp[u]; ++u; }
                for (; u + 4 <= t; u += 4) {
                    float4 v = nlp4[u >> 2];
                    acc += v.x; acc += v.y; acc += v.z; acc += v.w;
                }
                for (; u < t; ++u) acc += nlp[u];
                Lbuf[f * LROW + j] = acc;
                Lg[(size_t)t * NI + j] = acc;       // exact L for lazy backtrace
            }
        }
        __syncthreads();

        // Phase B: 28 frames x 82x82 max-plus, value only. 820 threads.
        if (tid < 820) {
            int trip = tid / NI;                 // 0..9, 3 frames each
            int j    = tid - trip * NI;
            int f0   = trip * 3;
            const float4* tr4 = (const float4*)(trans_c + j * TROW);
            const float4* L0  = (const float4*)(Lbuf + (f0 + 0) * LROW);
            const float4* L1  = (const float4*)(Lbuf + (f0 + 1) * LROW);
            const float4* L2  = (const float4*)(Lbuf + (f0 + 2) * LROW);
            float m0 = -1e30f, m1 = -1e30f, m2 = -1e30f;
#pragma unroll
            for (int g = 0; g < 21; ++g) {
                float4 tv = tr4[g];
                float4 x0 = L0[g];
                float4 x1 = L1[g];
                float4 x2 = L2[g];
                m0 = fmaxf(m0, x0.x + tv.x); m0 = fmaxf(m0, x0.y + tv.y);
                m0 = fmaxf(m0, x0.z + tv.z); m0 = fmaxf(m0, x0.w + tv.w);
                m1 = fmaxf(m1, x1.x + tv.x); m1 = fmaxf(m1, x1.y + tv.y);
                m1 = fmaxf(m1, x1.z + tv.z); m1 = fmaxf(m1, x1.w + tv.w);
                m2 = fmaxf(m2, x2.x + tv.x); m2 = fmaxf(m2, x2.y + tv.y);
                m2 = fmaxf(m2, x2.z + tv.z); m2 = fmaxf(m2, x2.w + tv.w);
            }
            int t = t0 + f0;
            if (f0 + 0 < NF) Fring[((t + 0) & (RING - 1)) * TROW + j] = m0 + blp[t + 0];
            if (f0 + 1 < NF) Fring[((t + 1) & (RING - 1)) * TROW + j] = m1 + blp[t + 1];
            if (f0 + 2 < NF) Fring[((t + 2) & (RING - 1)) * TROW + j] = m2 + blp[t + 2];
        }
        __syncthreads();
    }

    // ---- reconstruct delta_{T-1} exactly and argmax (first-max = smallest s) ----
    for (int t = tid; t < T_LEN; t += TPB) outb[t] = 0.0f;

    float bv = -INFINITY; int bs = 0x7fffffff;
    for (int s = tid; s < S_TOT; s += TPB) {
        int lo = 0, hi = 81;
        while (lo < hi) { int mid = (lo + hi + 1) >> 1; if (first_of(mid) <= s) lo = mid; else hi = mid - 1; }
        int j = lo;
        int p = s - first_of(j);
        float acc = Fring[((T_LEN - 1 - p) & (RING - 1)) * TROW + j];
        int u = T_LEN - p;
        while ((u & 3) && u < T_LEN) { acc += nlp[u]; ++u; }
        for (; u + 4 <= T_LEN; u += 4) {
            float4 v = nlp4[u >> 2];
            acc += v.x; acc += v.y; acc += v.z; acc += v.w;
        }
        for (; u < T_LEN; ++u) acc += nlp[u];
        if (acc > bv) { bv = acc; bs = s; }
    }
#pragma unroll
    for (int off = 16; off; off >>= 1) {
        float ov = __shfl_xor_sync(0xffffffffu, bv, off);
        int   oi = __shfl_xor_sync(0xffffffffu, bs, off);
        if (ov > bv || (ov == bv && oi < bs)) { bv = ov; bs = oi; }
    }
    if ((tid & 31) == 0) { redv[tid >> 5] = bv; redi[tid >> 5] = bs; }
    __syncthreads();

    // ---- warp-cooperative backtrace with lazy bp recovery ----
    if (tid < 32) {
        bv = redv[tid]; bs = redi[tid];
#pragma unroll
        for (int off = 16; off; off >>= 1) {
            float ov = __shfl_xor_sync(0xffffffffu, bv, off);
            int   oi = __shfl_xor_sync(0xffffffffu, bs, off);
            if (ov > bv || (ov == bv && oi < bs)) { bv = ov; bs = oi; }
        }
        int lo = 0, hi = 81;
        while (lo < hi) { int mid = (lo + hi + 1) >> 1; if (first_of(mid) <= bs) lo = mid; else hi = mid - 1; }
        int j   = lo;
        int pos = bs - first_of(j);
        int t   = T_LEN - 1;
        const int lane = tid;

        while (true) {
            int te = t - pos;                 // next (going back) frame with pos==0
            if (te < 0) break;
            if (lane == 0) {
                float x  = lg[te];
                float sg = 1.0f / (1.0f + expf(-x));
                if (sg >= 0.05f) outb[te] = 1.0f;
            }
            if (te == 0) break;
            // bp: first-max argmax_i  L_{te-1}[i] + trans[i][j]  (exact stored values)
            const float* Lr = Lg + (size_t)te * NI;
            float best = -INFINITY; int bi = 0x7fffffff;
            for (int i = lane; i < NI; i += 32) {
                float cc = Lr[i] + trans_c[j * TROW + i];
                if (cc > best) { best = cc; bi = i; }
            }
#pragma unroll
            for (int off = 16; off; off >>= 1) {
                float ov = __shfl_xor_sync(0xffffffffu, best, off);
                int   oi = __shfl_xor_sync(0xffffffffu, bi,   off);
                if (ov > best || (ov == best && oi < bi)) { best = ov; bi = oi; }
            }
            j   = bi;
            pos = 27 + j;                     // tau_j - 1
            t   = te - 1;
        }
    }
}

extern "C" void kernel_launch(void* const* d_in, const int* in_sizes, int n_in,
                              void* d_out, int out_size)
{
    (void)in_sizes; (void)n_in; (void)out_size;
    const float* logit = (const float*)d_in[0];
    float* out = (float*)d_out;

    const size_t smem = (size_t)(NI * TROW + RING * TROW + 30 * LROW + 2 * T_LEN + 32) * 4
                      + 32 * 4;
    cudaFuncSetAttribute(dbn_kernel,
                         cudaFuncAttributeMaxDynamicSharedMemorySize, (int)smem);
    dbn_kernel<<<BATCH, TPB, smem>>>(logit, out);
}